// round 4
// baseline (speedup 1.0000x reference)
#include <cuda_runtime.h>
#include <cstdint>

#define BB 4
#define LL 1024
#define DM 1024
#define SS 2048
#define NT 1000
#define HH 16
#define EE 256
#define DLLM 4096
#define HE 4096

// Scratch (device globals; no cudaMalloc allowed)
__device__ float g_Q[(size_t)BB * LL * HE];
__device__ float g_K[(size_t)SS * HE];
__device__ float g_V[(size_t)SS * HE];
__device__ float g_P[(size_t)BB * HH * LL * SS];
__device__ float g_O[(size_t)BB * LL * HE];

// ---------------------------------------------------------------------------
// Helpers
// ---------------------------------------------------------------------------
__device__ __forceinline__ uint32_t smem_u32(const void* p) {
    uint32_t a;
    asm("{ .reg .u64 t; cvta.to.shared.u64 t, %1; cvt.u32.u64 %0, t; }"
        : "=r"(a) : "l"(p));
    return a;
}

// Swizzled byte offset inside a [row][16k] f32 tile (row stride 64B).
// 16B chunk index c = k>>2 gets XORed with row bits so that ldmatrix phases
// (8 consecutive rows, fixed k-chunk) touch 8 distinct 16B lanes.
__device__ __forceinline__ uint32_t swz(int row, int k) {
    int c = ((k >> 2) ^ (row & 3) ^ ((row >> 2) & 3)) & 3;
    return (uint32_t)(row * 64 + c * 16 + (k & 3) * 4);
}

__device__ __forceinline__ void cp_async16(uint32_t dst, const void* src, int srcbytes) {
    asm volatile("cp.async.cg.shared.global [%0], [%1], 16, %2;"
                 :: "r"(dst), "l"(src), "r"(srcbytes) : "memory");
}
__device__ __forceinline__ void cp_commit() {
    asm volatile("cp.async.commit_group;" ::: "memory");
}
template <int N>
__device__ __forceinline__ void cp_wait() {
    asm volatile("cp.async.wait_group %0;" :: "n"(N) : "memory");
}

__device__ __forceinline__ void ldsm4(uint32_t* r, uint32_t addr) {
    asm volatile("ldmatrix.sync.aligned.m8n8.x4.shared.b16 {%0,%1,%2,%3}, [%4];"
                 : "=r"(r[0]), "=r"(r[1]), "=r"(r[2]), "=r"(r[3]) : "r"(addr));
}
__device__ __forceinline__ uint32_t to_tf32(uint32_t x) {
    uint32_t y;
    asm("cvt.rna.tf32.f32 %0, %1;" : "=r"(y) : "f"(__uint_as_float(x)));
    return y;
}
__device__ __forceinline__ void mma_tf32(float* d, const uint32_t* a, const uint32_t* b) {
    asm volatile(
        "mma.sync.aligned.m16n8k8.row.col.f32.tf32.tf32.f32 "
        "{%0,%1,%2,%3}, {%4,%5,%6,%7}, {%8,%9}, {%0,%1,%2,%3};"
        : "+f"(d[0]), "+f"(d[1]), "+f"(d[2]), "+f"(d[3])
        : "r"(a[0]), "r"(a[1]), "r"(a[2]), "r"(a[3]), "r"(b[0]), "r"(b[1]));
}

// ---------------------------------------------------------------------------
// tf32 mma.sync GEMM: C = scale * (A @ B^T) + bias
//   A: [M,K] row-major, row stride lda
//   B: logical [N,K]: element B[n*ldbn + k*ldbk]
//     BMODE 0: ldbk==1 (K-contiguous)  -> cp.async staging
//     BMODE 1: ldbn==1 (N-contiguous)  -> transposing LDG/STS staging
// CTA tile 128x128x16, 256 threads (8 warps: 2 in M x 4 in N, warp tile 64x32)
// Requires M%128==0, N%128==0.
// ---------------------------------------------------------------------------
#define Bb_M 128
#define Bb_N 128
#define Bb_K 16
#define TILE_BYTES (BB_UNUSED)

template <int BMODE>
__global__ __launch_bounds__(256)
void mma_gemm(int M, int N, int K,
              const float* __restrict__ A, long long lda,
              const float* __restrict__ B, long long ldbn, long long ldbk,
              float* __restrict__ C, long long ldc,
              const float* __restrict__ bias, float scale, int batchH,
              long long sA1, long long sA2,
              long long sB1, long long sB2,
              long long sC1, long long sC2)
{
    __shared__ __align__(128) float smA[2][Bb_M * Bb_K];
    __shared__ __align__(128) float smB[2][Bb_N * Bb_K];

    const int z  = blockIdx.z;
    const int zb = z / batchH;
    const int zh = z - zb * batchH;
    A += zb * sA1 + zh * sA2;
    B += zb * sB1 + zh * sB2;
    C += zb * sC1 + zh * sC2;

    const int bm = blockIdx.y * Bb_M;
    const int bn = blockIdx.x * Bb_N;

    const int tid = threadIdx.x;
    const int wid = tid >> 5;
    const int l   = tid & 31;
    const int warp_m = wid & 1;       // 2 warps in M
    const int warp_n = wid >> 1;      // 4 warps in N

    const uint32_t baseA = smem_u32(&smA[0][0]);
    const uint32_t baseB = smem_u32(&smB[0][0]);

    // ldmatrix per-thread source coordinates
    const int rowA = warp_m * 64 + (l & 7) + ((l >> 3) & 1) * 8;
    const int rowB = warp_n * 32 + (l & 7) + ((l >> 4) & 1) * 8;
    uint32_t adrA[2][2], adrB[2][2];
#pragma unroll
    for (int buf = 0; buf < 2; buf++)
#pragma unroll
        for (int ks = 0; ks < 2; ks++) {
            adrA[buf][ks] = baseA + buf * (Bb_M * Bb_K * 4)
                          + swz(rowA, ks * 8 + ((l >> 4) & 1) * 4);
            adrB[buf][ks] = baseB + buf * (Bb_N * Bb_K * 4)
                          + swz(rowB, ks * 8 + ((l >> 3) & 1) * 4);
        }

    const int T = (K + Bb_K - 1) / Bb_K;

    float d[4][4][4];
#pragma unroll
    for (int i = 0; i < 4; i++)
#pragma unroll
        for (int j = 0; j < 4; j++)
#pragma unroll
            for (int v = 0; v < 4; v++) d[i][j][v] = 0.0f;

    auto load_tile = [&](int t, int buf) {
        const int k0 = t * Bb_K;
        // A: 128 rows x 4 16B-chunks = 512 chunks, 2 per thread
#pragma unroll
        for (int i = 0; i < 2; i++) {
            int idx = tid + i * 256;
            int row = idx >> 2, c = idx & 3;
            int gk = k0 + c * 4;
            int rem = K - gk;
            int bytes = rem >= 4 ? 16 : (rem > 0 ? rem * 4 : 0);
            const float* src = A + (long long)(bm + row) * lda + (gk < K ? gk : 0);
            cp_async16(baseA + buf * (Bb_M * Bb_K * 4) + swz(row, c * 4), src, bytes);
        }
        if (BMODE == 0) {
#pragma unroll
            for (int i = 0; i < 2; i++) {
                int idx = tid + i * 256;
                int row = idx >> 2, c = idx & 3;
                int gk = k0 + c * 4;
                int rem = K - gk;
                int bytes = rem >= 4 ? 16 : (rem > 0 ? rem * 4 : 0);
                const float* src = B + (long long)(bn + row) * ldbn + (gk < K ? gk : 0);
                cp_async16(baseB + buf * (Bb_N * Bb_K * 4) + swz(row, c * 4), src, bytes);
            }
        } else {
            // transposing staging: LDG float4 along N, scatter STS
#pragma unroll
            for (int i = 0; i < 2; i++) {
                int idx = tid + i * 256;
                int kk = idx >> 5, n4 = idx & 31;
                int gk = k0 + kk;
                float4 v = make_float4(0.f, 0.f, 0.f, 0.f);
                if (gk < K) v = *(const float4*)(B + (long long)gk * ldbk + bn + n4 * 4);
                float* sb = &smB[buf][0];
                *(float*)((char*)sb + swz(n4 * 4 + 0, kk)) = v.x;
                *(float*)((char*)sb + swz(n4 * 4 + 1, kk)) = v.y;
                *(float*)((char*)sb + swz(n4 * 4 + 2, kk)) = v.z;
                *(float*)((char*)sb + swz(n4 * 4 + 3, kk)) = v.w;
            }
        }
    };

    // prologue
    load_tile(0, 0);
    cp_commit();

    for (int t = 0; t < T; t++) {
        const int cur = t & 1, nxt = cur ^ 1;
        if (t + 1 < T) {
            load_tile(t + 1, nxt);
            cp_commit();
            cp_wait<1>();
        } else {
            cp_wait<0>();
        }
        __syncthreads();

        // compute on buffer cur
#pragma unroll
        for (int ks = 0; ks < 2; ks++) {
            uint32_t a[4][4];
            uint32_t bfr[4][2];
#pragma unroll
            for (int mf = 0; mf < 4; mf++)
                ldsm4(a[mf], adrA[cur][ks] + mf * 1024);
            {
                uint32_t tmp[4];
                ldsm4(tmp, adrB[cur][ks]);
                bfr[0][0] = tmp[0]; bfr[0][1] = tmp[1];
                bfr[1][0] = tmp[2]; bfr[1][1] = tmp[3];
                ldsm4(tmp, adrB[cur][ks] + 1024);
                bfr[2][0] = tmp[0]; bfr[2][1] = tmp[1];
                bfr[3][0] = tmp[2]; bfr[3][1] = tmp[3];
            }
#pragma unroll
            for (int mf = 0; mf < 4; mf++)
#pragma unroll
                for (int v = 0; v < 4; v++) a[mf][v] = to_tf32(a[mf][v]);
#pragma unroll
            for (int nf = 0; nf < 4; nf++) {
                bfr[nf][0] = to_tf32(bfr[nf][0]);
                bfr[nf][1] = to_tf32(bfr[nf][1]);
            }
#pragma unroll
            for (int mf = 0; mf < 4; mf++)
#pragma unroll
                for (int nf = 0; nf < 4; nf++)
                    mma_tf32(d[mf][nf], a[mf], bfr[nf]);
        }
        __syncthreads();
    }

    // epilogue: scale + bias, float2 stores
    const int gid = l >> 2, tig = l & 3;
#pragma unroll
    for (int mf = 0; mf < 4; mf++) {
        const int row0 = bm + warp_m * 64 + mf * 16 + gid;
#pragma unroll
        for (int nf = 0; nf < 4; nf++) {
            const int col = bn + warp_n * 32 + nf * 8 + tig * 2;
            float bx = 0.f, by = 0.f;
            if (bias) {
                float2 bv = *(const float2*)(bias + col);
                bx = bv.x; by = bv.y;
            }
            float2 v0, v1;
            v0.x = d[mf][nf][0] * scale + bx;
            v0.y = d[mf][nf][1] * scale + by;
            v1.x = d[mf][nf][2] * scale + bx;
            v1.y = d[mf][nf][3] * scale + by;
            *(float2*)(C + (long long)row0 * ldc + col) = v0;
            *(float2*)(C + (long long)(row0 + 8) * ldc + col) = v1;
        }
    }
}

// ---------------------------------------------------------------------------
// Single-pass softmax over 2048 columns (one row per CTA, 256 threads)
// ---------------------------------------------------------------------------
__global__ __launch_bounds__(256)
void softmax_kernel(float* __restrict__ P)
{
    float* p = P + (long long)blockIdx.x * SS;
    const int t = threadIdx.x;
    const int w = t >> 5, l = t & 31;
    __shared__ float red[8];

    float4 a = ((const float4*)p)[t];
    float4 b = ((const float4*)p)[t + 256];

    float m = fmaxf(fmaxf(fmaxf(a.x, a.y), fmaxf(a.z, a.w)),
                    fmaxf(fmaxf(b.x, b.y), fmaxf(b.z, b.w)));
#pragma unroll
    for (int o = 16; o > 0; o >>= 1) m = fmaxf(m, __shfl_xor_sync(0xFFFFFFFF, m, o));
    if (l == 0) red[w] = m;
    __syncthreads();
    m = red[0];
#pragma unroll
    for (int i = 1; i < 8; i++) m = fmaxf(m, red[i]);
    __syncthreads();

    a.x = __expf(a.x - m); a.y = __expf(a.y - m); a.z = __expf(a.z - m); a.w = __expf(a.w - m);
    b.x = __expf(b.x - m); b.y = __expf(b.y - m); b.z = __expf(b.z - m); b.w = __expf(b.w - m);
    float s = a.x + a.y + a.z + a.w + b.x + b.y + b.z + b.w;
#pragma unroll
    for (int o = 16; o > 0; o >>= 1) s += __shfl_xor_sync(0xFFFFFFFF, s, o);
    if (l == 0) red[w] = s;
    __syncthreads();
    s = red[0];
#pragma unroll
    for (int i = 1; i < 8; i++) s += red[i];
    const float inv = 1.0f / s;

    a.x *= inv; a.y *= inv; a.z *= inv; a.w *= inv;
    b.x *= inv; b.y *= inv; b.z *= inv; b.w *= inv;
    ((float4*)p)[t] = a;
    ((float4*)p)[t + 256] = b;
}

// ---------------------------------------------------------------------------
// Host side
// ---------------------------------------------------------------------------
static void launch_mm(int bmode, int M, int N, int K,
                      const float* A, long long lda, long long sA1, long long sA2,
                      const float* B, long long ldbn, long long ldbk,
                      long long sB1, long long sB2,
                      float* C, long long ldc, long long sC1, long long sC2,
                      const float* bias, float scale, int batch, int batchH)
{
    dim3 grid(N / Bb_N, M / Bb_M, batch);
    if (bmode == 0)
        mma_gemm<0><<<grid, 256>>>(M, N, K, A, lda, B, ldbn, ldbk, C, ldc,
                                   bias, scale, batchH,
                                   sA1, sA2, sB1, sB2, sC1, sC2);
    else
        mma_gemm<1><<<grid, 256>>>(M, N, K, A, lda, B, ldbn, ldbk, C, ldc,
                                   bias, scale, batchH,
                                   sA1, sA2, sB1, sB2, sC1, sC2);
}

extern "C" void kernel_launch(void* const* d_in, const int* in_sizes, int n_in,
                              void* d_out, int out_size)
{
    const float* tgt = (const float*)d_in[0];   // [B,L,DM]
    const float* src = (const float*)d_in[1];   // [S,NT]
    const float* val = (const float*)d_in[2];   // [S,NT]
    const float* Wq  = (const float*)d_in[3];   // [HE,DM]
    const float* bq  = (const float*)d_in[4];
    const float* Wk  = (const float*)d_in[5];   // [HE,NT]
    const float* bk  = (const float*)d_in[6];
    const float* Wv  = (const float*)d_in[7];   // [HE,NT]
    const float* bv  = (const float*)d_in[8];
    const float* Wo  = (const float*)d_in[9];   // [DLLM,HE]
    const float* bo  = (const float*)d_in[10];
    float* out = (float*)d_out;                 // [B*L, DLLM]

    float *Qp, *Kp, *Vp, *Pp, *Op;
    cudaGetSymbolAddress((void**)&Qp, g_Q);
    cudaGetSymbolAddress((void**)&Kp, g_K);
    cudaGetSymbolAddress((void**)&Vp, g_V);
    cudaGetSymbolAddress((void**)&Pp, g_P);
    cudaGetSymbolAddress((void**)&Op, g_O);

    // 1. Q = tgt @ Wq^T + bq   [4096, 4096], K=1024
    launch_mm(0, BB * LL, HE, DM,
              tgt, DM, 0, 0,
              Wq, DM, 1, 0, 0,
              Qp, HE, 0, 0,
              bq, 1.0f, 1, 1);

    // 2. K = src @ Wk^T + bk   [2048, 4096], K=1000
    launch_mm(0, SS, HE, NT,
              src, NT, 0, 0,
              Wk, NT, 1, 0, 0,
              Kp, HE, 0, 0,
              bk, 1.0f, 1, 1);

    // 3. V = val @ Wv^T + bv   [2048, 4096], K=1000
    launch_mm(0, SS, HE, NT,
              val, NT, 0, 0,
              Wv, NT, 1, 0, 0,
              Vp, HE, 0, 0,
              bv, 1.0f, 1, 1);

    // 4. scores: P[b,h] = (1/16) * Q_bh [L,E] @ K_h [S,E]^T   (batch 64)
    launch_mm(0, LL, SS, EE,
              Qp, HE, (long long)LL * HE, EE,
              Kp, HE, 1, 0, EE,
              Pp, SS, (long long)HH * LL * SS, (long long)LL * SS,
              nullptr, 1.0f / 16.0f, BB * HH, HH);

    // 5. softmax over S
    softmax_kernel<<<BB * HH * LL, 256>>>(Pp);

    // 6. O_bh [L,E] = P[b,h] [L,S] @ V_h [S,E]   (transposing B staging, batch 64)
    launch_mm(1, LL, EE, SS,
              Pp, SS, (long long)HH * LL * SS, (long long)LL * SS,
              Vp, 1, HE, 0, EE,
              Op, HE, (long long)LL * HE, EE,
              nullptr, 1.0f, BB * HH, HH);

    // 7. out = O @ Wo^T + bo   [4096, 4096], K=4096
    launch_mm(0, BB * LL, DLLM, HE,
              Op, HE, 0, 0,
              Wo, HE, 1, 0, 0,
              out, DLLM, 0, 0,
              bo, 1.0f, 1, 1);
}

// round 5
// speedup vs baseline: 1.1493x; 1.1493x over previous
#include <cuda_runtime.h>
#include <cstdint>

#define BB 4
#define LL 1024
#define DM 1024
#define SS 2048
#define NT 1000
#define HH 16
#define EE 256
#define DLLM 4096
#define HE 4096

// Scratch (device globals; no cudaMalloc allowed)
__device__ float g_Q[(size_t)BB * LL * HE];
__device__ float g_K[(size_t)SS * HE];
__device__ float g_V[(size_t)SS * HE];
__device__ float g_P[(size_t)BB * HH * LL * SS];
__device__ float g_O[(size_t)BB * LL * HE];

// Pre-rounded (tf32) copies of the raw inputs, concatenated:
// tgt(4194304) src(2048000) val(2048000) Wq(4194304) Wk(4096000) Wv(4096000) Wo(16777216)
#define OFF_TGT 0
#define OFF_SRC (OFF_TGT + 4194304)
#define OFF_VAL (OFF_SRC + 2048000)
#define OFF_WQ  (OFF_VAL + 2048000)
#define OFF_WK  (OFF_WQ  + 4194304)
#define OFF_WV  (OFF_WK  + 4096000)
#define OFF_WO  (OFF_WV  + 4096000)
#define IN_TOTAL (OFF_WO + 16777216)
__device__ float g_IN[(size_t)IN_TOTAL];

// ---------------------------------------------------------------------------
// Helpers
// ---------------------------------------------------------------------------
__device__ __forceinline__ uint32_t smem_u32(const void* p) {
    uint32_t a;
    asm("{ .reg .u64 t; cvta.to.shared.u64 t, %1; cvt.u32.u64 %0, t; }"
        : "=r"(a) : "l"(p));
    return a;
}

// Swizzled byte offset inside a [row][16k] f32 tile (row stride 64B).
__device__ __forceinline__ uint32_t swz(int row, int k) {
    int c = ((k >> 2) ^ (row & 3) ^ ((row >> 2) & 3)) & 3;
    return (uint32_t)(row * 64 + c * 16 + (k & 3) * 4);
}

__device__ __forceinline__ void cp_async16(uint32_t dst, const void* src, int srcbytes) {
    asm volatile("cp.async.cg.shared.global [%0], [%1], 16, %2;"
                 :: "r"(dst), "l"(src), "r"(srcbytes) : "memory");
}
__device__ __forceinline__ void cp_commit() {
    asm volatile("cp.async.commit_group;" ::: "memory");
}
template <int N>
__device__ __forceinline__ void cp_wait() {
    asm volatile("cp.async.wait_group %0;" :: "n"(N) : "memory");
}
__device__ __forceinline__ void ldsm4(uint32_t* r, uint32_t addr) {
    asm volatile("ldmatrix.sync.aligned.m8n8.x4.shared.b16 {%0,%1,%2,%3}, [%4];"
                 : "=r"(r[0]), "=r"(r[1]), "=r"(r[2]), "=r"(r[3]) : "r"(addr));
}
__device__ __forceinline__ float rnd_tf32(float x) {
    uint32_t y;
    asm("cvt.rna.tf32.f32 %0, %1;" : "=r"(y) : "f"(x));
    return __uint_as_float(y);
}
__device__ __forceinline__ void mma_tf32(float* d, const uint32_t* a, const uint32_t* b) {
    asm volatile(
        "mma.sync.aligned.m16n8k8.row.col.f32.tf32.tf32.f32 "
        "{%0,%1,%2,%3}, {%4,%5,%6,%7}, {%8,%9}, {%0,%1,%2,%3};"
        : "+f"(d[0]), "+f"(d[1]), "+f"(d[2]), "+f"(d[3])
        : "r"(a[0]), "r"(a[1]), "r"(a[2]), "r"(a[3]), "r"(b[0]), "r"(b[1]));
}
__device__ __forceinline__ void sts_f32(uint32_t addr, float v) {
    asm volatile("st.shared.f32 [%0], %1;" :: "r"(addr), "f"(v) : "memory");
}

// ---------------------------------------------------------------------------
// tf32 rounding copy (one-time pre-pass over raw inputs)
// ---------------------------------------------------------------------------
__global__ __launch_bounds__(256)
void round_copy4(const float4* __restrict__ in, float4* __restrict__ out, int n4)
{
    int i = blockIdx.x * 256 + threadIdx.x;
    if (i < n4) {
        float4 v = in[i];
        v.x = rnd_tf32(v.x); v.y = rnd_tf32(v.y);
        v.z = rnd_tf32(v.z); v.w = rnd_tf32(v.w);
        out[i] = v;
    }
}

// ---------------------------------------------------------------------------
// tf32 mma.sync GEMM: C = scale * (A @ B^T) + bias  (all operands pre-rounded)
//   BMODE 0: B[n*ldbn + k], K-contiguous  -> cp.async staging
//   BMODE 1: B[n + k*ldbk], N-contiguous  -> transposing LDG/STS staging
// CTA tile 128x128x16, 256 threads (2x4 warps, warp tile 64x32).
// round_out: round stored C values to tf32 (for intermediates reused as inputs)
// ---------------------------------------------------------------------------
#define Bb_M 128
#define Bb_N 128
#define Bb_K 16
#define A_TILE_B (Bb_M * Bb_K * 4)
#define B_TILE_B (Bb_N * Bb_K * 4)

template <int BMODE>
__global__ __launch_bounds__(256)
void mma_gemm(int M, int N, int K,
              const float* __restrict__ A, long long lda,
              const float* __restrict__ B, long long ldbn, long long ldbk,
              float* __restrict__ C, long long ldc,
              const float* __restrict__ bias, float scale, int round_out,
              int batchH,
              long long sA1, long long sA2,
              long long sB1, long long sB2,
              long long sC1, long long sC2)
{
    __shared__ __align__(128) float smA[2][Bb_M * Bb_K];
    __shared__ __align__(128) float smB[2][Bb_N * Bb_K];

    const int z  = blockIdx.z;
    const int zb = z / batchH;
    const int zh = z - zb * batchH;
    A += zb * sA1 + zh * sA2;
    B += zb * sB1 + zh * sB2;
    C += zb * sC1 + zh * sC2;

    const int bm = blockIdx.y * Bb_M;
    const int bn = blockIdx.x * Bb_N;

    const int tid = threadIdx.x;
    const int wid = tid >> 5;
    const int l   = tid & 31;
    const int warp_m = wid & 1;
    const int warp_n = wid >> 1;

    const uint32_t baseA = smem_u32(&smA[0][0]);
    const uint32_t baseB = smem_u32(&smB[0][0]);

    // ---- hoisted ldmatrix addresses ----
    const int rowA = warp_m * 64 + (l & 7) + ((l >> 3) & 1) * 8;
    const int rowB = warp_n * 32 + (l & 7) + ((l >> 4) & 1) * 8;
    uint32_t adrA[2][2], adrB[2][2];
#pragma unroll
    for (int buf = 0; buf < 2; buf++)
#pragma unroll
        for (int ks = 0; ks < 2; ks++) {
            adrA[buf][ks] = baseA + buf * A_TILE_B + swz(rowA, ks * 8 + ((l >> 4) & 1) * 4);
            adrB[buf][ks] = baseB + buf * B_TILE_B + swz(rowB, ks * 8 + ((l >> 3) & 1) * 4);
        }

    // ---- hoisted staging addresses ----
    const float* pA[2]; uint32_t dA[2]; int kA[2];
#pragma unroll
    for (int i = 0; i < 2; i++) {
        int idx = tid + i * 256;
        int row = idx >> 2, c = idx & 3;
        kA[i] = c * 4;
        pA[i] = A + (long long)(bm + row) * lda + c * 4;
        dA[i] = baseA + swz(row, c * 4);
    }
    const float* pB0[2]; uint32_t dB0[2]; int kB0[2];
    const float* pB1[2]; uint32_t dB1[2][4]; int kB1[2];
    if (BMODE == 0) {
#pragma unroll
        for (int i = 0; i < 2; i++) {
            int idx = tid + i * 256;
            int row = idx >> 2, c = idx & 3;
            kB0[i] = c * 4;
            pB0[i] = B + (long long)(bn + row) * ldbn + c * 4;
            dB0[i] = baseB + swz(row, c * 4);
        }
    } else {
#pragma unroll
        for (int i = 0; i < 2; i++) {
            int idx = tid + i * 256;
            int kk = idx >> 5, n4 = idx & 31;
            kB1[i] = kk;
            pB1[i] = B + (long long)kk * ldbk + bn + n4 * 4;
#pragma unroll
            for (int j = 0; j < 4; j++)
                dB1[i][j] = baseB + swz(n4 * 4 + j, kk);
        }
    }

    const int T = (K + Bb_K - 1) / Bb_K;

    float d[4][4][4];
#pragma unroll
    for (int i = 0; i < 4; i++)
#pragma unroll
        for (int j = 0; j < 4; j++)
#pragma unroll
            for (int v = 0; v < 4; v++) d[i][j][v] = 0.0f;

    auto load_tile = [&](int t, int buf) {
        const int k0 = t * Bb_K;
        const uint32_t bo = buf ? A_TILE_B : 0;
#pragma unroll
        for (int i = 0; i < 2; i++) {
            int rem = K - k0 - kA[i];
            int bytes = rem >= 4 ? 16 : (rem > 0 ? rem * 4 : 0);
            cp_async16(dA[i] + bo, pA[i] + k0, bytes);
        }
        if (BMODE == 0) {
            const uint32_t boB = buf ? B_TILE_B : 0;
#pragma unroll
            for (int i = 0; i < 2; i++) {
                int rem = K - k0 - kB0[i];
                int bytes = rem >= 4 ? 16 : (rem > 0 ? rem * 4 : 0);
                cp_async16(dB0[i] + boB, pB0[i] + k0, bytes);
            }
        } else {
            const uint32_t boB = buf ? B_TILE_B : 0;
#pragma unroll
            for (int i = 0; i < 2; i++) {
                float4 v = make_float4(0.f, 0.f, 0.f, 0.f);
                if (k0 + kB1[i] < K) v = *(const float4*)(pB1[i] + (long long)k0 * ldbk);
                sts_f32(dB1[i][0] + boB, v.x);
                sts_f32(dB1[i][1] + boB, v.y);
                sts_f32(dB1[i][2] + boB, v.z);
                sts_f32(dB1[i][3] + boB, v.w);
            }
        }
    };

    load_tile(0, 0);
    cp_commit();

    for (int t = 0; t < T; t++) {
        const int cur = t & 1, nxt = cur ^ 1;
        if (t + 1 < T) {
            load_tile(t + 1, nxt);
            cp_commit();
            cp_wait<1>();
        } else {
            cp_wait<0>();
        }
        __syncthreads();

#pragma unroll
        for (int ks = 0; ks < 2; ks++) {
            uint32_t a[4][4];
            uint32_t bfr[4][2];
#pragma unroll
            for (int mf = 0; mf < 4; mf++)
                ldsm4(a[mf], adrA[cur][ks] + mf * 1024);
            {
                uint32_t tmp[4];
                ldsm4(tmp, adrB[cur][ks]);
                bfr[0][0] = tmp[0]; bfr[0][1] = tmp[1];
                bfr[1][0] = tmp[2]; bfr[1][1] = tmp[3];
                ldsm4(tmp, adrB[cur][ks] + 1024);
                bfr[2][0] = tmp[0]; bfr[2][1] = tmp[1];
                bfr[3][0] = tmp[2]; bfr[3][1] = tmp[3];
            }
#pragma unroll
            for (int mf = 0; mf < 4; mf++)
#pragma unroll
                for (int nf = 0; nf < 4; nf++)
                    mma_tf32(d[mf][nf], a[mf], bfr[nf]);
        }
        __syncthreads();
    }

    // epilogue
    const int gid = l >> 2, tig = l & 3;
#pragma unroll
    for (int mf = 0; mf < 4; mf++) {
        const int row0 = bm + warp_m * 64 + mf * 16 + gid;
#pragma unroll
        for (int nf = 0; nf < 4; nf++) {
            const int col = bn + warp_n * 32 + nf * 8 + tig * 2;
            float bx = 0.f, by = 0.f;
            if (bias) {
                float2 bv = *(const float2*)(bias + col);
                bx = bv.x; by = bv.y;
            }
            float2 v0, v1;
            v0.x = d[mf][nf][0] * scale + bx;
            v0.y = d[mf][nf][1] * scale + by;
            v1.x = d[mf][nf][2] * scale + bx;
            v1.y = d[mf][nf][3] * scale + by;
            if (round_out) {
                v0.x = rnd_tf32(v0.x); v0.y = rnd_tf32(v0.y);
                v1.x = rnd_tf32(v1.x); v1.y = rnd_tf32(v1.y);
            }
            *(float2*)(C + (long long)row0 * ldc + col) = v0;
            *(float2*)(C + (long long)(row0 + 8) * ldc + col) = v1;
        }
    }
}

// ---------------------------------------------------------------------------
// Single-pass softmax over 2048 columns; output rounded to tf32
// ---------------------------------------------------------------------------
__global__ __launch_bounds__(256)
void softmax_kernel(float* __restrict__ P)
{
    float* p = P + (long long)blockIdx.x * SS;
    const int t = threadIdx.x;
    const int w = t >> 5, l = t & 31;
    __shared__ float red[8];

    float4 a = ((const float4*)p)[t];
    float4 b = ((const float4*)p)[t + 256];

    float m = fmaxf(fmaxf(fmaxf(a.x, a.y), fmaxf(a.z, a.w)),
                    fmaxf(fmaxf(b.x, b.y), fmaxf(b.z, b.w)));
#pragma unroll
    for (int o = 16; o > 0; o >>= 1) m = fmaxf(m, __shfl_xor_sync(0xFFFFFFFF, m, o));
    if (l == 0) red[w] = m;
    __syncthreads();
    m = red[0];
#pragma unroll
    for (int i = 1; i < 8; i++) m = fmaxf(m, red[i]);
    __syncthreads();

    a.x = __expf(a.x - m); a.y = __expf(a.y - m); a.z = __expf(a.z - m); a.w = __expf(a.w - m);
    b.x = __expf(b.x - m); b.y = __expf(b.y - m); b.z = __expf(b.z - m); b.w = __expf(b.w - m);
    float s = a.x + a.y + a.z + a.w + b.x + b.y + b.z + b.w;
#pragma unroll
    for (int o = 16; o > 0; o >>= 1) s += __shfl_xor_sync(0xFFFFFFFF, s, o);
    if (l == 0) red[w] = s;
    __syncthreads();
    s = red[0];
#pragma unroll
    for (int i = 1; i < 8; i++) s += red[i];
    const float inv = 1.0f / s;

    a.x = rnd_tf32(a.x * inv); a.y = rnd_tf32(a.y * inv);
    a.z = rnd_tf32(a.z * inv); a.w = rnd_tf32(a.w * inv);
    b.x = rnd_tf32(b.x * inv); b.y = rnd_tf32(b.y * inv);
    b.z = rnd_tf32(b.z * inv); b.w = rnd_tf32(b.w * inv);
    ((float4*)p)[t] = a;
    ((float4*)p)[t + 256] = b;
}

// ---------------------------------------------------------------------------
// Host side
// ---------------------------------------------------------------------------
static void launch_mm(int bmode, int M, int N, int K,
                      const float* A, long long lda, long long sA1, long long sA2,
                      const float* B, long long ldbn, long long ldbk,
                      long long sB1, long long sB2,
                      float* C, long long ldc, long long sC1, long long sC2,
                      const float* bias, float scale, int round_out,
                      int batch, int batchH)
{
    dim3 grid(N / Bb_N, M / Bb_M, batch);
    if (bmode == 0)
        mma_gemm<0><<<grid, 256>>>(M, N, K, A, lda, B, ldbn, ldbk, C, ldc,
                                   bias, scale, round_out, batchH,
                                   sA1, sA2, sB1, sB2, sC1, sC2);
    else
        mma_gemm<1><<<grid, 256>>>(M, N, K, A, lda, B, ldbn, ldbk, C, ldc,
                                   bias, scale, round_out, batchH,
                                   sA1, sA2, sB1, sB2, sC1, sC2);
}

static void launch_round(const float* in, float* out, long long n)
{
    int n4 = (int)(n / 4);
    round_copy4<<<(n4 + 255) / 256, 256>>>((const float4*)in, (float4*)out, n4);
}

extern "C" void kernel_launch(void* const* d_in, const int* in_sizes, int n_in,
                              void* d_out, int out_size)
{
    const float* tgt = (const float*)d_in[0];
    const float* src = (const float*)d_in[1];
    const float* val = (const float*)d_in[2];
    const float* Wq  = (const float*)d_in[3];
    const float* bq  = (const float*)d_in[4];
    const float* Wk  = (const float*)d_in[5];
    const float* bk  = (const float*)d_in[6];
    const float* Wv  = (const float*)d_in[7];
    const float* bv  = (const float*)d_in[8];
    const float* Wo  = (const float*)d_in[9];
    const float* bo  = (const float*)d_in[10];
    float* out = (float*)d_out;

    float *Qp, *Kp, *Vp, *Pp, *Op, *INp;
    cudaGetSymbolAddress((void**)&Qp, g_Q);
    cudaGetSymbolAddress((void**)&Kp, g_K);
    cudaGetSymbolAddress((void**)&Vp, g_V);
    cudaGetSymbolAddress((void**)&Pp, g_P);
    cudaGetSymbolAddress((void**)&Op, g_O);
    cudaGetSymbolAddress((void**)&INp, g_IN);

    // Pre-round raw inputs to tf32 (one-time copies)
    launch_round(tgt, INp + OFF_TGT, 4194304);
    launch_round(src, INp + OFF_SRC, 2048000);
    launch_round(val, INp + OFF_VAL, 2048000);
    launch_round(Wq,  INp + OFF_WQ,  4194304);
    launch_round(Wk,  INp + OFF_WK,  4096000);
    launch_round(Wv,  INp + OFF_WV,  4096000);
    launch_round(Wo,  INp + OFF_WO,  16777216);

    const float* rtgt = INp + OFF_TGT;
    const float* rsrc = INp + OFF_SRC;
    const float* rval = INp + OFF_VAL;
    const float* rWq  = INp + OFF_WQ;
    const float* rWk  = INp + OFF_WK;
    const float* rWv  = INp + OFF_WV;
    const float* rWo  = INp + OFF_WO;

    // 1. Q = tgt @ Wq^T + bq   [4096, 4096], K=1024  (output rounded)
    launch_mm(0, BB * LL, HE, DM,
              rtgt, DM, 0, 0,
              rWq, DM, 1, 0, 0,
              Qp, HE, 0, 0,
              bq, 1.0f, 1, 1, 1);

    // 2. K = src @ Wk^T + bk   [2048, 4096], K=1000  (output rounded)
    launch_mm(0, SS, HE, NT,
              rsrc, NT, 0, 0,
              rWk, NT, 1, 0, 0,
              Kp, HE, 0, 0,
              bk, 1.0f, 1, 1, 1);

    // 3. V = val @ Wv^T + bv   [2048, 4096], K=1000  (output rounded)
    launch_mm(0, SS, HE, NT,
              rval, NT, 0, 0,
              rWv, NT, 1, 0, 0,
              Vp, HE, 0, 0,
              bv, 1.0f, 1, 1, 1);

    // 4. scores: P[b,h] = (1/16) * Q_bh @ K_h^T   (batch 64; softmax rounds P)
    launch_mm(0, LL, SS, EE,
              Qp, HE, (long long)LL * HE, EE,
              Kp, HE, 1, 0, EE,
              Pp, SS, (long long)HH * LL * SS, (long long)LL * SS,
              nullptr, 1.0f / 16.0f, 0, BB * HH, HH);

    // 5. softmax over S (rounds output to tf32)
    softmax_kernel<<<BB * HH * LL, 256>>>(Pp);

    // 6. O_bh = P[b,h] @ V_h   (transposing B staging, batch 64; output rounded)
    launch_mm(1, LL, EE, SS,
              Pp, SS, (long long)HH * LL * SS, (long long)LL * SS,
              Vp, 1, HE, 0, EE,
              Op, HE, (long long)LL * HE, EE,
              nullptr, 1.0f, 1, BB * HH, HH);

    // 7. out = O @ Wo^T + bo   [4096, 4096], K=4096  (final output NOT rounded)
    launch_mm(0, BB * LL, DLLM, HE,
              Op, HE, 0, 0,
              rWo, HE, 1, 0, 0,
              out, DLLM, 0, 0,
              bo, 1.0f, 0, 1, 1);
}

// round 6
// speedup vs baseline: 1.1522x; 1.0026x over previous
#include <cuda_runtime.h>
#include <cstdint>

#define BB 4
#define LL 1024
#define DM 1024
#define SS 2048
#define NT 1000
#define HH 16
#define EE 256
#define DLLM 4096
#define HE 4096

// Scratch (device globals; no cudaMalloc allowed)
__device__ float g_Q[(size_t)BB * LL * HE];
__device__ float g_K[(size_t)SS * HE];
__device__ float g_V[(size_t)SS * HE];
__device__ float g_P[(size_t)BB * HH * LL * SS];
__device__ float g_O[(size_t)BB * LL * HE];

// Pre-rounded (tf32) copies of the raw inputs, concatenated:
// tgt(4194304) src(2048000) val(2048000) Wq(4194304) Wk(4096000) Wv(4096000) Wo(16777216)
#define OFF_TGT 0
#define OFF_SRC (OFF_TGT + 4194304)
#define OFF_VAL (OFF_SRC + 2048000)
#define OFF_WQ  (OFF_VAL + 2048000)
#define OFF_WK  (OFF_WQ  + 4194304)
#define OFF_WV  (OFF_WK  + 4096000)
#define OFF_WO  (OFF_WV  + 4096000)
#define IN_TOTAL (OFF_WO + 16777216)
__device__ float g_IN[(size_t)IN_TOTAL];

// ---------------------------------------------------------------------------
// Helpers
// ---------------------------------------------------------------------------
__device__ __forceinline__ uint32_t smem_u32(const void* p) {
    uint32_t a;
    asm("{ .reg .u64 t; cvta.to.shared.u64 t, %1; cvt.u32.u64 %0, t; }"
        : "=r"(a) : "l"(p));
    return a;
}

// Swizzled byte offset inside a [row][16k] f32 tile (row stride 64B).
__device__ __forceinline__ uint32_t swz(int row, int k) {
    int c = ((k >> 2) ^ (row & 3) ^ ((row >> 2) & 3)) & 3;
    return (uint32_t)(row * 64 + c * 16 + (k & 3) * 4);
}

__device__ __forceinline__ void cp_async16(uint32_t dst, const void* src, int srcbytes) {
    asm volatile("cp.async.cg.shared.global [%0], [%1], 16, %2;"
                 :: "r"(dst), "l"(src), "r"(srcbytes) : "memory");
}
__device__ __forceinline__ void cp_commit() {
    asm volatile("cp.async.commit_group;" ::: "memory");
}
template <int N>
__device__ __forceinline__ void cp_wait() {
    asm volatile("cp.async.wait_group %0;" :: "n"(N) : "memory");
}
__device__ __forceinline__ void ldsm4(uint32_t* r, uint32_t addr) {
    asm volatile("ldmatrix.sync.aligned.m8n8.x4.shared.b16 {%0,%1,%2,%3}, [%4];"
                 : "=r"(r[0]), "=r"(r[1]), "=r"(r[2]), "=r"(r[3]) : "r"(addr));
}
__device__ __forceinline__ float rnd_tf32(float x) {
    uint32_t y;
    asm("cvt.rna.tf32.f32 %0, %1;" : "=r"(y) : "f"(x));
    return __uint_as_float(y);
}
__device__ __forceinline__ void mma_tf32(float* d, const uint32_t* a, const uint32_t* b) {
    asm volatile(
        "mma.sync.aligned.m16n8k8.row.col.f32.tf32.tf32.f32 "
        "{%0,%1,%2,%3}, {%4,%5,%6,%7}, {%8,%9}, {%0,%1,%2,%3};"
        : "+f"(d[0]), "+f"(d[1]), "+f"(d[2]), "+f"(d[3])
        : "r"(a[0]), "r"(a[1]), "r"(a[2]), "r"(a[3]), "r"(b[0]), "r"(b[1]));
}
__device__ __forceinline__ void sts_f32(uint32_t addr, float v) {
    asm volatile("st.shared.f32 [%0], %1;" :: "r"(addr), "f"(v) : "memory");
}

// ---------------------------------------------------------------------------
// tf32 rounding copy (one-time pre-pass over raw inputs)
// ---------------------------------------------------------------------------
__global__ __launch_bounds__(256)
void round_copy4(const float4* __restrict__ in, float4* __restrict__ out, int n4)
{
    int i = blockIdx.x * 256 + threadIdx.x;
    if (i < n4) {
        float4 v = in[i];
        v.x = rnd_tf32(v.x); v.y = rnd_tf32(v.y);
        v.z = rnd_tf32(v.z); v.w = rnd_tf32(v.w);
        out[i] = v;
    }
}

// ---------------------------------------------------------------------------
// tf32 mma.sync GEMM: C = scale * (A @ B^T) + bias  (all operands pre-rounded)
//   BMODE 0: B[n*ldbn + k], K-contiguous  -> cp.async staging
//   BMODE 1: B[n + k*ldbk], N-contiguous  -> transposing LDG/STS staging
// CTA tile 128x128x16, 256 threads (2x4 warps, warp tile 64x32).
// round_out: round stored C values to tf32 (for intermediates reused as inputs)
// ---------------------------------------------------------------------------
#define Bb_M 128
#define Bb_N 128
#define Bb_K 16
#define A_TILE_B (Bb_M * Bb_K * 4)
#define B_TILE_B (Bb_N * Bb_K * 4)

template <int BMODE>
__global__ __launch_bounds__(256)
void mma_gemm(int M, int N, int K,
              const float* __restrict__ A, long long lda,
              const float* __restrict__ B, long long ldbn, long long ldbk,
              float* __restrict__ C, long long ldc,
              const float* __restrict__ bias, float scale, int round_out,
              int batchH,
              long long sA1, long long sA2,
              long long sB1, long long sB2,
              long long sC1, long long sC2)
{
    __shared__ __align__(128) float smA[2][Bb_M * Bb_K];
    __shared__ __align__(128) float smB[2][Bb_N * Bb_K];

    const int z  = blockIdx.z;
    const int zb = z / batchH;
    const int zh = z - zb * batchH;
    A += zb * sA1 + zh * sA2;
    B += zb * sB1 + zh * sB2;
    C += zb * sC1 + zh * sC2;

    const int bm = blockIdx.y * Bb_M;
    const int bn = blockIdx.x * Bb_N;

    const int tid = threadIdx.x;
    const int wid = tid >> 5;
    const int l   = tid & 31;
    const int warp_m = wid & 1;
    const int warp_n = wid >> 1;

    const uint32_t baseA = smem_u32(&smA[0][0]);
    const uint32_t baseB = smem_u32(&smB[0][0]);

    // ---- hoisted ldmatrix addresses ----
    const int rowA = warp_m * 64 + (l & 7) + ((l >> 3) & 1) * 8;
    const int rowB = warp_n * 32 + (l & 7) + ((l >> 4) & 1) * 8;
    uint32_t adrA[2][2], adrB[2][2];
#pragma unroll
    for (int buf = 0; buf < 2; buf++)
#pragma unroll
        for (int ks = 0; ks < 2; ks++) {
            adrA[buf][ks] = baseA + buf * A_TILE_B + swz(rowA, ks * 8 + ((l >> 4) & 1) * 4);
            adrB[buf][ks] = baseB + buf * B_TILE_B + swz(rowB, ks * 8 + ((l >> 3) & 1) * 4);
        }

    // ---- hoisted staging addresses ----
    const float* pA[2]; uint32_t dA[2]; int kA[2];
#pragma unroll
    for (int i = 0; i < 2; i++) {
        int idx = tid + i * 256;
        int row = idx >> 2, c = idx & 3;
        kA[i] = c * 4;
        pA[i] = A + (long long)(bm + row) * lda + c * 4;
        dA[i] = baseA + swz(row, c * 4);
    }
    const float* pB0[2]; uint32_t dB0[2]; int kB0[2];
    const float* pB1[2]; uint32_t dB1[2][4]; int kB1[2];
    if (BMODE == 0) {
#pragma unroll
        for (int i = 0; i < 2; i++) {
            int idx = tid + i * 256;
            int row = idx >> 2, c = idx & 3;
            kB0[i] = c * 4;
            pB0[i] = B + (long long)(bn + row) * ldbn + c * 4;
            dB0[i] = baseB + swz(row, c * 4);
        }
    } else {
#pragma unroll
        for (int i = 0; i < 2; i++) {
            int idx = tid + i * 256;
            int kk = idx >> 5, n4 = idx & 31;
            kB1[i] = kk;
            pB1[i] = B + (long long)kk * ldbk + bn + n4 * 4;
#pragma unroll
            for (int j = 0; j < 4; j++)
                dB1[i][j] = baseB + swz(n4 * 4 + j, kk);
        }
    }

    const int T = (K + Bb_K - 1) / Bb_K;

    float d[4][4][4];
#pragma unroll
    for (int i = 0; i < 4; i++)
#pragma unroll
        for (int j = 0; j < 4; j++)
#pragma unroll
            for (int v = 0; v < 4; v++) d[i][j][v] = 0.0f;

    auto load_tile = [&](int t, int buf) {
        const int k0 = t * Bb_K;
        const uint32_t bo = buf ? A_TILE_B : 0;
#pragma unroll
        for (int i = 0; i < 2; i++) {
            int rem = K - k0 - kA[i];
            int bytes = rem >= 4 ? 16 : (rem > 0 ? rem * 4 : 0);
            cp_async16(dA[i] + bo, pA[i] + k0, bytes);
        }
        if (BMODE == 0) {
            const uint32_t boB = buf ? B_TILE_B : 0;
#pragma unroll
            for (int i = 0; i < 2; i++) {
                int rem = K - k0 - kB0[i];
                int bytes = rem >= 4 ? 16 : (rem > 0 ? rem * 4 : 0);
                cp_async16(dB0[i] + boB, pB0[i] + k0, bytes);
            }
        } else {
            const uint32_t boB = buf ? B_TILE_B : 0;
#pragma unroll
            for (int i = 0; i < 2; i++) {
                float4 v = make_float4(0.f, 0.f, 0.f, 0.f);
                if (k0 + kB1[i] < K) v = *(const float4*)(pB1[i] + (long long)k0 * ldbk);
                sts_f32(dB1[i][0] + boB, v.x);
                sts_f32(dB1[i][1] + boB, v.y);
                sts_f32(dB1[i][2] + boB, v.z);
                sts_f32(dB1[i][3] + boB, v.w);
            }
        }
    };

    load_tile(0, 0);
    cp_commit();

    for (int t = 0; t < T; t++) {
        const int cur = t & 1, nxt = cur ^ 1;
        if (t + 1 < T) {
            load_tile(t + 1, nxt);
            cp_commit();
            cp_wait<1>();
        } else {
            cp_wait<0>();
        }
        __syncthreads();

#pragma unroll
        for (int ks = 0; ks < 2; ks++) {
            uint32_t a[4][4];
            uint32_t bfr[4][2];
#pragma unroll
            for (int mf = 0; mf < 4; mf++)
                ldsm4(a[mf], adrA[cur][ks] + mf * 1024);
            {
                uint32_t tmp[4];
                ldsm4(tmp, adrB[cur][ks]);
                bfr[0][0] = tmp[0]; bfr[0][1] = tmp[1];
                bfr[1][0] = tmp[2]; bfr[1][1] = tmp[3];
                ldsm4(tmp, adrB[cur][ks] + 1024);
                bfr[2][0] = tmp[0]; bfr[2][1] = tmp[1];
                bfr[3][0] = tmp[2]; bfr[3][1] = tmp[3];
            }
#pragma unroll
            for (int mf = 0; mf < 4; mf++)
#pragma unroll
                for (int nf = 0; nf < 4; nf++)
                    mma_tf32(d[mf][nf], a[mf], bfr[nf]);
        }
        __syncthreads();
    }

    // epilogue
    const int gid = l >> 2, tig = l & 3;
#pragma unroll
    for (int mf = 0; mf < 4; mf++) {
        const int row0 = bm + warp_m * 64 + mf * 16 + gid;
#pragma unroll
        for (int nf = 0; nf < 4; nf++) {
            const int col = bn + warp_n * 32 + nf * 8 + tig * 2;
            float bx = 0.f, by = 0.f;
            if (bias) {
                float2 bv = *(const float2*)(bias + col);
                bx = bv.x; by = bv.y;
            }
            float2 v0, v1;
            v0.x = d[mf][nf][0] * scale + bx;
            v0.y = d[mf][nf][1] * scale + by;
            v1.x = d[mf][nf][2] * scale + bx;
            v1.y = d[mf][nf][3] * scale + by;
            if (round_out) {
                v0.x = rnd_tf32(v0.x); v0.y = rnd_tf32(v0.y);
                v1.x = rnd_tf32(v1.x); v1.y = rnd_tf32(v1.y);
            }
            *(float2*)(C + (long long)row0 * ldc + col) = v0;
            *(float2*)(C + (long long)(row0 + 8) * ldc + col) = v1;
        }
    }
}

// ---------------------------------------------------------------------------
// Single-pass softmax over 2048 columns; output rounded to tf32
// ---------------------------------------------------------------------------
__global__ __launch_bounds__(256)
void softmax_kernel(float* __restrict__ P)
{
    float* p = P + (long long)blockIdx.x * SS;
    const int t = threadIdx.x;
    const int w = t >> 5, l = t & 31;
    __shared__ float red[8];

    float4 a = ((const float4*)p)[t];
    float4 b = ((const float4*)p)[t + 256];

    float m = fmaxf(fmaxf(fmaxf(a.x, a.y), fmaxf(a.z, a.w)),
                    fmaxf(fmaxf(b.x, b.y), fmaxf(b.z, b.w)));
#pragma unroll
    for (int o = 16; o > 0; o >>= 1) m = fmaxf(m, __shfl_xor_sync(0xFFFFFFFF, m, o));
    if (l == 0) red[w] = m;
    __syncthreads();
    m = red[0];
#pragma unroll
    for (int i = 1; i < 8; i++) m = fmaxf(m, red[i]);
    __syncthreads();

    a.x = __expf(a.x - m); a.y = __expf(a.y - m); a.z = __expf(a.z - m); a.w = __expf(a.w - m);
    b.x = __expf(b.x - m); b.y = __expf(b.y - m); b.z = __expf(b.z - m); b.w = __expf(b.w - m);
    float s = a.x + a.y + a.z + a.w + b.x + b.y + b.z + b.w;
#pragma unroll
    for (int o = 16; o > 0; o >>= 1) s += __shfl_xor_sync(0xFFFFFFFF, s, o);
    if (l == 0) red[w] = s;
    __syncthreads();
    s = red[0];
#pragma unroll
    for (int i = 1; i < 8; i++) s += red[i];
    const float inv = 1.0f / s;

    a.x = rnd_tf32(a.x * inv); a.y = rnd_tf32(a.y * inv);
    a.z = rnd_tf32(a.z * inv); a.w = rnd_tf32(a.w * inv);
    b.x = rnd_tf32(b.x * inv); b.y = rnd_tf32(b.y * inv);
    b.z = rnd_tf32(b.z * inv); b.w = rnd_tf32(b.w * inv);
    ((float4*)p)[t] = a;
    ((float4*)p)[t + 256] = b;
}

// ---------------------------------------------------------------------------
// Host side
// ---------------------------------------------------------------------------
static void launch_mm(int bmode, int M, int N, int K,
                      const float* A, long long lda, long long sA1, long long sA2,
                      const float* B, long long ldbn, long long ldbk,
                      long long sB1, long long sB2,
                      float* C, long long ldc, long long sC1, long long sC2,
                      const float* bias, float scale, int round_out,
                      int batch, int batchH)
{
    dim3 grid(N / Bb_N, M / Bb_M, batch);
    if (bmode == 0)
        mma_gemm<0><<<grid, 256>>>(M, N, K, A, lda, B, ldbn, ldbk, C, ldc,
                                   bias, scale, round_out, batchH,
                                   sA1, sA2, sB1, sB2, sC1, sC2);
    else
        mma_gemm<1><<<grid, 256>>>(M, N, K, A, lda, B, ldbn, ldbk, C, ldc,
                                   bias, scale, round_out, batchH,
                                   sA1, sA2, sB1, sB2, sC1, sC2);
}

static void launch_round(const float* in, float* out, long long n)
{
    int n4 = (int)(n / 4);
    round_copy4<<<(n4 + 255) / 256, 256>>>((const float4*)in, (float4*)out, n4);
}

extern "C" void kernel_launch(void* const* d_in, const int* in_sizes, int n_in,
                              void* d_out, int out_size)
{
    const float* tgt = (const float*)d_in[0];
    const float* src = (const float*)d_in[1];
    const float* val = (const float*)d_in[2];
    const float* Wq  = (const float*)d_in[3];
    const float* bq  = (const float*)d_in[4];
    const float* Wk  = (const float*)d_in[5];
    const float* bk  = (const float*)d_in[6];
    const float* Wv  = (const float*)d_in[7];
    const float* bv  = (const float*)d_in[8];
    const float* Wo  = (const float*)d_in[9];
    const float* bo  = (const float*)d_in[10];
    float* out = (float*)d_out;

    float *Qp, *Kp, *Vp, *Pp, *Op, *INp;
    cudaGetSymbolAddress((void**)&Qp, g_Q);
    cudaGetSymbolAddress((void**)&Kp, g_K);
    cudaGetSymbolAddress((void**)&Vp, g_V);
    cudaGetSymbolAddress((void**)&Pp, g_P);
    cudaGetSymbolAddress((void**)&Op, g_O);
    cudaGetSymbolAddress((void**)&INp, g_IN);

    // Pre-round raw inputs to tf32 (one-time copies)
    launch_round(tgt, INp + OFF_TGT, 4194304);
    launch_round(src, INp + OFF_SRC, 2048000);
    launch_round(val, INp + OFF_VAL, 2048000);
    launch_round(Wq,  INp + OFF_WQ,  4194304);
    launch_round(Wk,  INp + OFF_WK,  4096000);
    launch_round(Wv,  INp + OFF_WV,  4096000);
    launch_round(Wo,  INp + OFF_WO,  16777216);

    const float* rtgt = INp + OFF_TGT;
    const float* rsrc = INp + OFF_SRC;
    const float* rval = INp + OFF_VAL;
    const float* rWq  = INp + OFF_WQ;
    const float* rWk  = INp + OFF_WK;
    const float* rWv  = INp + OFF_WV;
    const float* rWo  = INp + OFF_WO;

    // 1. Q = tgt @ Wq^T + bq   [4096, 4096], K=1024  (output rounded)
    launch_mm(0, BB * LL, HE, DM,
              rtgt, DM, 0, 0,
              rWq, DM, 1, 0, 0,
              Qp, HE, 0, 0,
              bq, 1.0f, 1, 1, 1);

    // 2. K = src @ Wk^T + bk   [2048, 4096], K=1000  (output rounded)
    launch_mm(0, SS, HE, NT,
              rsrc, NT, 0, 0,
              rWk, NT, 1, 0, 0,
              Kp, HE, 0, 0,
              bk, 1.0f, 1, 1, 1);

    // 3. V = val @ Wv^T + bv   [2048, 4096], K=1000  (output rounded)
    launch_mm(0, SS, HE, NT,
              rval, NT, 0, 0,
              rWv, NT, 1, 0, 0,
              Vp, HE, 0, 0,
              bv, 1.0f, 1, 1, 1);

    // 4. scores: P[b,h] = (1/16) * Q_bh @ K_h^T   (batch 64; softmax rounds P)
    launch_mm(0, LL, SS, EE,
              Qp, HE, (long long)LL * HE, EE,
              Kp, HE, 1, 0, EE,
              Pp, SS, (long long)HH * LL * SS, (long long)LL * SS,
              nullptr, 1.0f / 16.0f, 0, BB * HH, HH);

    // 5. softmax over S (rounds output to tf32)
    softmax_kernel<<<BB * HH * LL, 256>>>(Pp);

    // 6. O_bh = P[b,h] @ V_h   (transposing B staging, batch 64; output rounded)
    launch_mm(1, LL, EE, SS,
              Pp, SS, (long long)HH * LL * SS, (long long)LL * SS,
              Vp, 1, HE, 0, EE,
              Op, HE, (long long)LL * HE, EE,
              nullptr, 1.0f, 1, BB * HH, HH);

    // 7. out = O @ Wo^T + bo   [4096, 4096], K=4096  (final output NOT rounded)
    launch_mm(0, BB * LL, DLLM, HE,
              Op, HE, 0, 0,
              rWo, HE, 1, 0, 0,
              out, DLLM, 0, 0,
              bo, 1.0f, 0, 1, 1);
}